// round 4
// baseline (speedup 1.0000x reference)
#include <cuda_runtime.h>

#define B_  256
#define T_  500
#define I_  700
#define O_  400
#define M_  (B_ * T_)          // 128000 GEMM rows

// scratch for h = inputs @ W^T   [M_, O_] row-major == [B,T,O]
__device__ float g_h[(size_t)M_ * O_];

#define BM 128
#define BN 64
#define BK 16

// ---- packed f32x2 helpers (PTX-only; ptxas never auto-fuses these) ----
typedef unsigned long long ull;

__device__ __forceinline__ ull fma2(ull a, ull b, ull c) {
    ull d;
    asm("fma.rn.f32x2 %0, %1, %2, %3;" : "=l"(d) : "l"(a), "l"(b), "l"(c));
    return d;
}
__device__ __forceinline__ ull add2(ull a, ull b) {
    ull d;
    asm("add.rn.f32x2 %0, %1, %2;" : "=l"(d) : "l"(a), "l"(b));
    return d;
}
__device__ __forceinline__ ull pack2(float lo, float hi) {
    ull d;
    asm("mov.b64 %0, {%1, %2};" : "=l"(d) : "f"(lo), "f"(hi));
    return d;
}
__device__ __forceinline__ void unpack2(ull v, float& lo, float& hi) {
    asm("mov.b64 {%0, %1}, %2;" : "=f"(lo), "=f"(hi) : "l"(v));
}

// Packed Kahan step, bitwise-identical (per lane) to:
//   y = fma(a,b,-comp); t = s + y; comp = (t - s) - y; s = t
// State c holds NEGATED compensation (c = -comp):
//   y  = fma(a,b,c)                       ; a*b - comp
//   t  = s + y
//   nt = -t            (exact sign flip via XOR, alu pipe)
//   c  = (s + nt) + y  ; = -( (t - s) - y ) by RN sign symmetry
//   s  = t
#define KAHAN2(s, c, a, b)                                   \
    do {                                                     \
        ull y_  = fma2((a), (b), (c));                       \
        ull t_  = add2((s), y_);                             \
        ull nt_ = t_ ^ 0x8000000080000000ULL;                \
        (c) = add2(add2((s), nt_), y_);                      \
        (s) = t_;                                            \
    } while (0)

__global__ __launch_bounds__(256) void snn_gemm_kahan2_kernel(const float* __restrict__ A,
                                                              const float* __restrict__ Wm) {
    __shared__ float As[BK][BM + 4];
    __shared__ float Bs[BK][BN + 4];

    const int K = I_;
    const int N = O_;
    const int bm = blockIdx.x * BM;
    const int bn = blockIdx.y * BN;
    const int tid = threadIdx.x;
    const int tx = tid & 15;   // N direction, 4 cols each (2 packed pairs)
    const int ty = tid >> 4;   // M direction, 8 rows each

    ull acc[8][2];   // packed sums, j-pairs (0,1) and (2,3)
    ull cmp[8][2];   // packed NEGATED compensations
    #pragma unroll
    for (int i = 0; i < 8; i++)
        #pragma unroll
        for (int j = 0; j < 2; j++) { acc[i][j] = 0ULL; cmp[i][j] = 0ULL; }

    for (int k0 = 0; k0 < K; k0 += BK) {
        // ---- load A tile: 128 rows x 16 k, 2 float4 per thread ----
        #pragma unroll
        for (int i = 0; i < 2; i++) {
            int q   = tid + i * 256;
            int row = q >> 2;            // 0..127
            int kq  = (q & 3) * 4;       // 0,4,8,12
            const float* src = A + (size_t)(bm + row) * K + k0 + kq;
            float4 v;
            if (k0 + kq + 3 < K) {
                v = *reinterpret_cast<const float4*>(src);
            } else {
                v.x = (k0 + kq + 0 < K) ? src[0] : 0.0f;
                v.y = (k0 + kq + 1 < K) ? src[1] : 0.0f;
                v.z = (k0 + kq + 2 < K) ? src[2] : 0.0f;
                v.w = (k0 + kq + 3 < K) ? src[3] : 0.0f;
            }
            As[kq + 0][row] = v.x;
            As[kq + 1][row] = v.y;
            As[kq + 2][row] = v.z;
            As[kq + 3][row] = v.w;
        }
        // ---- load W tile: 64 rows x 16 k, 1 float4 per thread ----
        {
            int q   = tid;
            int row = q >> 2;            // 0..63
            int kq  = (q & 3) * 4;
            int n   = bn + row;
            float4 v = make_float4(0.f, 0.f, 0.f, 0.f);
            if (n < N) {
                const float* src = Wm + (size_t)n * K + k0 + kq;
                if (k0 + kq + 3 < K) {
                    v = *reinterpret_cast<const float4*>(src);
                } else {
                    v.x = (k0 + kq + 0 < K) ? src[0] : 0.0f;
                    v.y = (k0 + kq + 1 < K) ? src[1] : 0.0f;
                    v.z = (k0 + kq + 2 < K) ? src[2] : 0.0f;
                    v.w = (k0 + kq + 3 < K) ? src[3] : 0.0f;
                }
            }
            Bs[kq + 0][row] = v.x;
            Bs[kq + 1][row] = v.y;
            Bs[kq + 2][row] = v.z;
            Bs[kq + 3][row] = v.w;
        }
        __syncthreads();

        // ---- compute: packed Kahan, ascending-k chain per accumulator ----
        #pragma unroll
        for (int kk = 0; kk < BK; kk++) {
            float4 a0 = *reinterpret_cast<const float4*>(&As[kk][ty * 8]);
            float4 a1 = *reinterpret_cast<const float4*>(&As[kk][ty * 8 + 4]);
            float4 bb = *reinterpret_cast<const float4*>(&Bs[kk][tx * 4]);
            ull b01 = pack2(bb.x, bb.y);
            ull b23 = pack2(bb.z, bb.w);
            float a[8] = {a0.x, a0.y, a0.z, a0.w, a1.x, a1.y, a1.z, a1.w};
            #pragma unroll
            for (int i = 0; i < 8; i++) {
                ull aa = pack2(a[i], a[i]);
                KAHAN2(acc[i][0], cmp[i][0], aa, b01);
                KAHAN2(acc[i][1], cmp[i][1], aa, b23);
            }
        }
        __syncthreads();
    }

    // ---- store ----
    #pragma unroll
    for (int i = 0; i < 8; i++) {
        int m = bm + ty * 8 + i;
        float* dst = g_h + (size_t)m * N;
        float v0, v1, v2, v3;
        unpack2(acc[i][0], v0, v1);
        unpack2(acc[i][1], v2, v3);
        int n = bn + tx * 4;
        if (n + 0 < N) dst[n + 0] = v0;
        if (n + 1 < N) dst[n + 1] = v1;
        if (n + 2 < N) dst[n + 2] = v2;
        if (n + 3 < N) dst[n + 3] = v3;
    }
}

// One thread per (b, o) neuron; sequential over t. (Unchanged from passing R3.)
__global__ __launch_bounds__(256) void snn_scan_kernel(float* __restrict__ out) {
    int idx = blockIdx.x * blockDim.x + threadIdx.x;
    if (idx >= B_ * O_) return;
    int b = idx / O_;
    int o = idx - b * O_;

    const float* hp = g_h + (size_t)b * T_ * O_ + o;
    float* op = out + (size_t)b * T_ * O_ + o;

    float syn = 0.0f, mem = 0.0f;
    #pragma unroll 4
    for (int t = 0; t < T_; t++) {
        float ht = __ldg(hp + (size_t)t * O_);
        float s  = (mem > 1.0f) ? 1.0f : 0.0f;
        op[(size_t)t * O_] = s;
        float nsyn = __fmaf_rn(0.9f, syn, ht);
        float bmv  = __fmaf_rn(0.85f, mem, syn);
        mem = __fmul_rn(bmv, __fadd_rn(1.0f, -s));
        syn = nsyn;
    }
}

extern "C" void kernel_launch(void* const* d_in, const int* in_sizes, int n_in,
                              void* d_out, int out_size) {
    const float* inputs = (const float*)d_in[0];  // [256,500,700] f32
    const float* W      = (const float*)d_in[1];  // [400,700]     f32
    float* out          = (float*)d_out;          // [256,500,400] f32

    dim3 ggrid((M_ + BM - 1) / BM, (O_ + BN - 1) / BN);   // 1000 x 7
    snn_gemm_kahan2_kernel<<<ggrid, 256>>>(inputs, W);

    int n_neurons = B_ * O_;                               // 102400
    snn_scan_kernel<<<(n_neurons + 255) / 256, 256>>>(out);
}

// round 5
// speedup vs baseline: 1.8025x; 1.8025x over previous
#include <cuda_runtime.h>

#define B_  256
#define T_  500
#define I_  700
#define O_  400
#define M_  (B_ * T_)          // 128000 GEMM rows

// scratch for h = inputs @ W^T   [M_, O_] row-major == [B,T,O]
__device__ float g_h[(size_t)M_ * O_];

#define BM 128
#define BN 64
#define BK 16

// Chunk-compensated SGEMM:
//   - plain ascending-k FFMA chain within each BK=16 k-tile (1 op/MAC)
//   - Kahan-fold the tile partial into (acc, cmp) once per tile (4 FADD / 16 MACs)
// Error ~1.7u (vs ~1u full Kahan, ~15u plain-700 chain), well under the
// reference's own ~6u accumulation error, so spike flips stay at the
// reference-error floor.
__global__ __launch_bounds__(256) void snn_gemm_chunk_kernel(const float* __restrict__ A,
                                                             const float* __restrict__ Wm) {
    __shared__ float As[BK][BM + 4];
    __shared__ float Bs[BK][BN + 4];

    const int K = I_;
    const int N = O_;
    const int bm = blockIdx.x * BM;
    const int bn = blockIdx.y * BN;
    const int tid = threadIdx.x;
    const int tx = tid & 15;   // N direction, 4 cols each
    const int ty = tid >> 4;   // M direction, 8 rows each

    float acc[8][4];   // compensated master sums
    float cmp[8][4];   // Kahan compensations
    #pragma unroll
    for (int i = 0; i < 8; i++)
        #pragma unroll
        for (int j = 0; j < 4; j++) { acc[i][j] = 0.0f; cmp[i][j] = 0.0f; }

    for (int k0 = 0; k0 < K; k0 += BK) {
        // ---- load A tile: 128 rows x 16 k, 2 float4 per thread ----
        #pragma unroll
        for (int i = 0; i < 2; i++) {
            int q   = tid + i * 256;
            int row = q >> 2;            // 0..127
            int kq  = (q & 3) * 4;       // 0,4,8,12
            const float* src = A + (size_t)(bm + row) * K + k0 + kq;
            float4 v;
            if (k0 + kq + 3 < K) {
                v = *reinterpret_cast<const float4*>(src);
            } else {
                v.x = (k0 + kq + 0 < K) ? src[0] : 0.0f;
                v.y = (k0 + kq + 1 < K) ? src[1] : 0.0f;
                v.z = (k0 + kq + 2 < K) ? src[2] : 0.0f;
                v.w = (k0 + kq + 3 < K) ? src[3] : 0.0f;
            }
            As[kq + 0][row] = v.x;
            As[kq + 1][row] = v.y;
            As[kq + 2][row] = v.z;
            As[kq + 3][row] = v.w;
        }
        // ---- load W tile: 64 rows x 16 k, 1 float4 per thread ----
        {
            int q   = tid;
            int row = q >> 2;            // 0..63
            int kq  = (q & 3) * 4;
            int n   = bn + row;
            float4 v = make_float4(0.f, 0.f, 0.f, 0.f);
            if (n < N) {
                const float* src = Wm + (size_t)n * K + k0 + kq;
                if (k0 + kq + 3 < K) {
                    v = *reinterpret_cast<const float4*>(src);
                } else {
                    v.x = (k0 + kq + 0 < K) ? src[0] : 0.0f;
                    v.y = (k0 + kq + 1 < K) ? src[1] : 0.0f;
                    v.z = (k0 + kq + 2 < K) ? src[2] : 0.0f;
                    v.w = (k0 + kq + 3 < K) ? src[3] : 0.0f;
                }
            }
            Bs[kq + 0][row] = v.x;
            Bs[kq + 1][row] = v.y;
            Bs[kq + 2][row] = v.z;
            Bs[kq + 3][row] = v.w;
        }
        __syncthreads();

        // ---- inner: plain FFMA chain over this k-tile ----
        float p[8][4];
        #pragma unroll
        for (int i = 0; i < 8; i++)
            #pragma unroll
            for (int j = 0; j < 4; j++) p[i][j] = 0.0f;

        #pragma unroll
        for (int kk = 0; kk < BK; kk++) {
            float4 a0 = *reinterpret_cast<const float4*>(&As[kk][ty * 8]);
            float4 a1 = *reinterpret_cast<const float4*>(&As[kk][ty * 8 + 4]);
            float4 bb = *reinterpret_cast<const float4*>(&Bs[kk][tx * 4]);
            float a[8] = {a0.x, a0.y, a0.z, a0.w, a1.x, a1.y, a1.z, a1.w};
            float b[4] = {bb.x, bb.y, bb.z, bb.w};
            #pragma unroll
            for (int i = 0; i < 8; i++)
                #pragma unroll
                for (int j = 0; j < 4; j++)
                    p[i][j] = __fmaf_rn(a[i], b[j], p[i][j]);
        }

        // ---- Kahan-fold tile partial into master sum (4 FADD / 16 MACs) ----
        #pragma unroll
        for (int i = 0; i < 8; i++) {
            #pragma unroll
            for (int j = 0; j < 4; j++) {
                float y = __fadd_rn(p[i][j], -cmp[i][j]);
                float t = __fadd_rn(acc[i][j], y);
                cmp[i][j] = __fadd_rn(__fadd_rn(t, -acc[i][j]), -y);
                acc[i][j] = t;
            }
        }
        __syncthreads();
    }

    // ---- store ----
    #pragma unroll
    for (int i = 0; i < 8; i++) {
        int m = bm + ty * 8 + i;
        float* dst = g_h + (size_t)m * N;
        #pragma unroll
        for (int j = 0; j < 4; j++) {
            int n = bn + tx * 4 + j;
            if (n < N) dst[n] = acc[i][j];
        }
    }
}

// One thread per (b, o) neuron; sequential over t. (Unchanged from passing R3.)
__global__ __launch_bounds__(256) void snn_scan_kernel(float* __restrict__ out) {
    int idx = blockIdx.x * blockDim.x + threadIdx.x;
    if (idx >= B_ * O_) return;
    int b = idx / O_;
    int o = idx - b * O_;

    const float* hp = g_h + (size_t)b * T_ * O_ + o;
    float* op = out + (size_t)b * T_ * O_ + o;

    float syn = 0.0f, mem = 0.0f;
    #pragma unroll 4
    for (int t = 0; t < T_; t++) {
        float ht = __ldg(hp + (size_t)t * O_);
        float s  = (mem > 1.0f) ? 1.0f : 0.0f;
        op[(size_t)t * O_] = s;
        float nsyn = __fmaf_rn(0.9f, syn, ht);
        float bmv  = __fmaf_rn(0.85f, mem, syn);
        mem = __fmul_rn(bmv, __fadd_rn(1.0f, -s));
        syn = nsyn;
    }
}

extern "C" void kernel_launch(void* const* d_in, const int* in_sizes, int n_in,
                              void* d_out, int out_size) {
    const float* inputs = (const float*)d_in[0];  // [256,500,700] f32
    const float* W      = (const float*)d_in[1];  // [400,700]     f32
    float* out          = (float*)d_out;          // [256,500,400] f32

    dim3 ggrid((M_ + BM - 1) / BM, (O_ + BN - 1) / BN);   // 1000 x 7
    snn_gemm_chunk_kernel<<<ggrid, 256>>>(inputs, W);

    int n_neurons = B_ * O_;                               // 102400
    snn_scan_kernel<<<(n_neurons + 255) / 256, 256>>>(out);
}

// round 8
// speedup vs baseline: 3.6326x; 2.0154x over previous
#include <cuda_runtime.h>
#include <cuda_bf16.h>
#include <cstdint>

#define B_    256
#define T_    500
#define I_    700
#define O_    400
#define M_    (B_ * T_)        // 128000
#define KPAD  704
#define NPAD  448              // 7 tiles of 64
#define KCH   64
#define NCH   (KPAD / KCH)     // 11 k-chunks

// ---- device scratch (BSS zero-init; padding regions never written) ----
__device__ float         g_h [(size_t)M_ * O_];
__device__ __nv_bfloat16 g_A0[(size_t)M_ * KPAD];
__device__ __nv_bfloat16 g_A1[(size_t)M_ * KPAD];
__device__ __nv_bfloat16 g_A2[(size_t)M_ * KPAD];
__device__ __nv_bfloat16 g_W0[(size_t)NPAD * KPAD];
__device__ __nv_bfloat16 g_W1[(size_t)NPAD * KPAD];
__device__ __nv_bfloat16 g_W2[(size_t)NPAD * KPAD];

// ---- smem geometry (per stage): 3 A tiles (128 x 144B) + 3 B tiles (64 x 144B)
#define ROWB      144                    // 128B data + 16B pad (conflict-free ldmatrix)
#define A_TILE    (128 * ROWB)           // 18432
#define B_TILE    (64 * ROWB)            // 9216
#define STAGE     (3 * A_TILE + 3 * B_TILE)  // 82944
#define SMEM_SZ   (2 * STAGE)            // 165888

// ============================ PTX helpers ============================
__device__ __forceinline__ uint32_t smem_u32(const void* p) {
    uint32_t a;
    asm("{ .reg .u64 t; cvta.to.shared.u64 t, %1; cvt.u32.u64 %0, t; }" : "=r"(a) : "l"(p));
    return a;
}
__device__ __forceinline__ void cp16(uint32_t dst, const void* src) {
    asm volatile("cp.async.cg.shared.global [%0], [%1], 16;" :: "r"(dst), "l"(src) : "memory");
}
__device__ __forceinline__ void ldsm_x4(uint32_t* r, uint32_t addr) {
    asm volatile("ldmatrix.sync.aligned.m8n8.x4.shared.b16 {%0,%1,%2,%3}, [%4];"
        : "=r"(r[0]), "=r"(r[1]), "=r"(r[2]), "=r"(r[3]) : "r"(addr));
}
__device__ __forceinline__ void mma16816(float* d, const uint32_t* a, const uint32_t* b) {
    asm volatile("mma.sync.aligned.m16n8k16.row.col.f32.bf16.bf16.f32 "
        "{%0,%1,%2,%3}, {%4,%5,%6,%7}, {%8,%9}, {%0,%1,%2,%3};"
        : "+f"(d[0]), "+f"(d[1]), "+f"(d[2]), "+f"(d[3])
        : "r"(a[0]), "r"(a[1]), "r"(a[2]), "r"(a[3]), "r"(b[0]), "r"(b[1]));
}

// hmma over the warp tile: p[2][4][4], aF[2][4] (2 m-tiles), bF[2][4] (2 n-halves)
__device__ __forceinline__ void mma_tile(float* p, const uint32_t* aF, const uint32_t* bF) {
    #pragma unroll
    for (int mt = 0; mt < 2; mt++)
        #pragma unroll
        for (int nt = 0; nt < 4; nt++)
            mma16816(p + (mt * 4 + nt) * 4, aF + mt * 4, bF + (nt >> 1) * 4 + (nt & 1) * 2);
}

// ============================ kernels ============================

// 3-way bf16 split (a = a0 + a1 + a2, residual ~2^-33)
__global__ void convert_split3(const float* __restrict__ src,
                               __nv_bfloat16* __restrict__ d0,
                               __nv_bfloat16* __restrict__ d1,
                               __nv_bfloat16* __restrict__ d2) {
    size_t m = blockIdx.x;
    const float* s = src + m * I_;
    size_t off = m * KPAD;
    for (int k = threadIdx.x; k < I_; k += blockDim.x) {
        float a = s[k];
        __nv_bfloat16 b0 = __float2bfloat16_rn(a);
        float r1 = a - __bfloat162float(b0);
        __nv_bfloat16 b1 = __float2bfloat16_rn(r1);
        float r2 = r1 - __bfloat162float(b1);
        d0[off + k] = b0;
        d1[off + k] = b1;
        d2[off + k] = __float2bfloat16_rn(r2);
    }
}

// bf16x3-split emulated-fp32 GEMM on mma.sync tensor cores.
// CTA tile 128(M) x 64(N); 8 warps as 4(M) x 2(N), warp tile 32x32.
// Per 64-k chunk: all 6 product passes accumulate into register partial p,
// then Kahan-fold p into (acc, cmp). sigma_ours ~1.5u << sigma_ref ~5.3u.
// B smem is [n-row][k contiguous]; mma.row.col wants adjacent-k pairs per
// register for BOTH A and B -> NON-trans ldmatrix for both (R7 bug: .trans on B).
__global__ __launch_bounds__(256, 1) void snn_gemm_mma() {
    extern __shared__ char smem[];
    const uint32_t sb = smem_u32(smem);
    const int tid    = threadIdx.x;
    const int lane   = tid & 31;
    const int wid    = tid >> 5;
    const int warp_m = wid & 3;
    const int warp_n = wid >> 2;
    const int m0     = blockIdx.y * 128;
    const int n0     = blockIdx.x * 64;

    const __nv_bfloat16* gA[3] = {g_A0, g_A1, g_A2};
    const __nv_bfloat16* gB[3] = {g_W0, g_W1, g_W2};

    // per-thread ldmatrix address bases
    const uint32_t aoff = (uint32_t)(warp_m * 32 + (lane & 15)) * ROWB + ((lane >> 4) << 4);
    const uint32_t boff = (uint32_t)(warp_n * 32 + (lane & 7) + ((lane >> 4) << 3)) * ROWB
                        + (((lane >> 3) & 1) << 4);

    float acc[32], cmp[32];
    #pragma unroll
    for (int e = 0; e < 32; e++) { acc[e] = 0.0f; cmp[e] = 0.0f; }

    // ---- stage loader: 4608 x 16B cp.async, 18 per thread ----
    auto load_stage = [&](int stage, int chunk) {
        const int k0 = chunk * KCH;
        const uint32_t st = sb + stage * STAGE;
        #pragma unroll
        for (int it = 0; it < 18; it++) {
            int idx = tid + it * 256;
            if (idx < 3072) {                       // A tiles
                int i  = idx >> 10;
                int r  = (idx & 1023) >> 3;
                int cu = idx & 7;
                const void* src = (const char*)gA[i]
                    + (((size_t)(m0 + r) * KPAD + k0 + cu * 8) << 1);
                cp16(st + i * A_TILE + r * ROWB + cu * 16, src);
            } else {                                // B tiles
                int j  = (idx - 3072) >> 9;
                int r  = ((idx - 3072) & 511) >> 3;
                int cu = idx & 7;
                const void* src = (const char*)gB[j]
                    + (((size_t)(n0 + r) * KPAD + k0 + cu * 8) << 1);
                cp16(st + 3 * A_TILE + j * B_TILE + r * ROWB + cu * 16, src);
            }
        }
        asm volatile("cp.async.commit_group;" ::: "memory");
    };

    load_stage(0, 0);

    for (int c = 0; c < NCH; c++) {
        if (c + 1 < NCH) {
            load_stage((c + 1) & 1, c + 1);
            asm volatile("cp.async.wait_group 1;" ::: "memory");
        } else {
            asm volatile("cp.async.wait_group 0;" ::: "memory");
        }
        __syncthreads();

        const uint32_t st = sb + (c & 1) * STAGE;
        const uint32_t aB = st + aoff;
        const uint32_t bB = st + 3 * A_TILE + boff;

        float p[32];
        #pragma unroll
        for (int e = 0; e < 32; e++) p[e] = 0.0f;

        #pragma unroll
        for (int step = 0; step < 4; step++) {
            const uint32_t ks = step * 32;   // 16 k-elems = 32 bytes
            uint32_t aF0[8], aFx[8], bF0[8], bFx[8];
            // A0, A1 (2 m-tiles each); B0, B1 (2 n-halves each) — all NON-trans
            ldsm_x4(aF0 + 0, aB + 0 * A_TILE + 0 * 2304 + ks);
            ldsm_x4(aF0 + 4, aB + 0 * A_TILE + 1 * 2304 + ks);
            ldsm_x4(aFx + 0, aB + 1 * A_TILE + 0 * 2304 + ks);
            ldsm_x4(aFx + 4, aB + 1 * A_TILE + 1 * 2304 + ks);
            ldsm_x4(bF0 + 0, bB + 0 * B_TILE + 0 * 2304 + ks);
            ldsm_x4(bF0 + 4, bB + 0 * B_TILE + 1 * 2304 + ks);
            ldsm_x4(bFx + 0, bB + 1 * B_TILE + 0 * 2304 + ks);
            ldsm_x4(bFx + 4, bB + 1 * B_TILE + 1 * 2304 + ks);

            mma_tile(p, aF0, bF0);   // A0*B0
            mma_tile(p, aF0, bFx);   // A0*B1
            mma_tile(p, aFx, bF0);   // A1*B0
            mma_tile(p, aFx, bFx);   // A1*B1

            // reuse frag regs: A2, B2
            ldsm_x4(aFx + 0, aB + 2 * A_TILE + 0 * 2304 + ks);
            ldsm_x4(aFx + 4, aB + 2 * A_TILE + 1 * 2304 + ks);
            ldsm_x4(bFx + 0, bB + 2 * B_TILE + 0 * 2304 + ks);
            ldsm_x4(bFx + 4, bB + 2 * B_TILE + 1 * 2304 + ks);

            mma_tile(p, aF0, bFx);   // A0*B2
            mma_tile(p, aFx, bF0);   // A2*B0
        }

        // Kahan-fold chunk partial into master
        #pragma unroll
        for (int e = 0; e < 32; e++) {
            float y = __fadd_rn(p[e], -cmp[e]);
            float t = __fadd_rn(acc[e], y);
            cmp[e] = __fadd_rn(__fadd_rn(t, -acc[e]), -y);
            acc[e] = t;
        }
        __syncthreads();
    }

    // ---- store: c0,c1 at (row, col..col+1), c2,c3 at (row+8, same) ----
    #pragma unroll
    for (int mt = 0; mt < 2; mt++) {
        #pragma unroll
        for (int nt = 0; nt < 4; nt++) {
            const float* e = acc + (mt * 4 + nt) * 4;
            const float* k = cmp + (mt * 4 + nt) * 4;
            int m = m0 + warp_m * 32 + mt * 16 + (lane >> 2);
            int n = n0 + warp_n * 32 + nt * 8 + (lane & 3) * 2;
            if (n < O_) {
                float2 v0 = make_float2(__fadd_rn(e[0], -k[0]), __fadd_rn(e[1], -k[1]));
                float2 v1 = make_float2(__fadd_rn(e[2], -k[2]), __fadd_rn(e[3], -k[3]));
                *reinterpret_cast<float2*>(g_h + (size_t)m * O_ + n)       = v0;
                *reinterpret_cast<float2*>(g_h + (size_t)(m + 8) * O_ + n) = v1;
            }
        }
    }
}

// One thread per (b, o) neuron; sequential over t. (Unchanged from passing R3.)
__global__ __launch_bounds__(256) void snn_scan_kernel(float* __restrict__ out) {
    int idx = blockIdx.x * blockDim.x + threadIdx.x;
    if (idx >= B_ * O_) return;
    int b = idx / O_;
    int o = idx - b * O_;

    const float* hp = g_h + (size_t)b * T_ * O_ + o;
    float* op = out + (size_t)b * T_ * O_ + o;

    float syn = 0.0f, mem = 0.0f;
    #pragma unroll 4
    for (int t = 0; t < T_; t++) {
        float ht = __ldg(hp + (size_t)t * O_);
        float s  = (mem > 1.0f) ? 1.0f : 0.0f;
        op[(size_t)t * O_] = s;
        float nsyn = __fmaf_rn(0.9f, syn, ht);
        float bmv  = __fmaf_rn(0.85f, mem, syn);
        mem = __fmul_rn(bmv, __fadd_rn(1.0f, -s));
        syn = nsyn;
    }
}

// ============================ host ============================
extern "C" void kernel_launch(void* const* d_in, const int* in_sizes, int n_in,
                              void* d_out, int out_size) {
    const float* inputs = (const float*)d_in[0];  // [256,500,700] f32
    const float* W      = (const float*)d_in[1];  // [400,700]     f32
    float* out          = (float*)d_out;          // [256,500,400] f32

    void *pA0, *pA1, *pA2, *pW0, *pW1, *pW2;
    cudaGetSymbolAddress(&pA0, g_A0);
    cudaGetSymbolAddress(&pA1, g_A1);
    cudaGetSymbolAddress(&pA2, g_A2);
    cudaGetSymbolAddress(&pW0, g_W0);
    cudaGetSymbolAddress(&pW1, g_W1);
    cudaGetSymbolAddress(&pW2, g_W2);

    convert_split3<<<M_, 256>>>(inputs, (__nv_bfloat16*)pA0, (__nv_bfloat16*)pA1, (__nv_bfloat16*)pA2);
    convert_split3<<<O_, 256>>>(W,      (__nv_bfloat16*)pW0, (__nv_bfloat16*)pW1, (__nv_bfloat16*)pW2);

    cudaFuncSetAttribute(snn_gemm_mma, cudaFuncAttributeMaxDynamicSharedMemorySize, SMEM_SZ);
    dim3 grid(NPAD / 64, M_ / 128);   // 7 x 1000
    snn_gemm_mma<<<grid, 256, SMEM_SZ>>>();

    int n_neurons = B_ * O_;
    snn_scan_kernel<<<(n_neurons + 255) / 256, 256>>>(out);
}

// round 10
// speedup vs baseline: 3.7979x; 1.0455x over previous
#include <cuda_runtime.h>
#include <cuda_bf16.h>
#include <cstdint>

#define B_    256
#define T_    500
#define I_    700
#define O_    400
#define M_    (B_ * T_)        // 128000
#define KPAD  704
#define NPAD  448
#define MT    64               // CTA tile M
#define NT    224              // CTA tile N
#define KCH   32               // k per chunk
#define NCH   22               // 704/32

// ---- device scratch (BSS zero-init; padding regions stay 0) ----
__device__ float         g_h [(size_t)M_ * O_];
__device__ __nv_bfloat16 g_W0[(size_t)NPAD * KPAD];
__device__ __nv_bfloat16 g_W1[(size_t)NPAD * KPAD];
__device__ __nv_bfloat16 g_W2[(size_t)NPAD * KPAD];

// ---- smem geometry ----
#define ROWB     80                       // 64B k-data + 16B pad (ldmatrix conflict-free)
#define A32_BUF  8192                     // 64 rows x 128B fp32
#define SA_SPL   (MT * ROWB)              // 5120 per split
#define SB_SPL   (NT * ROWB)              // 17920 per split
#define SB_STAGE (3 * SB_SPL)             // 53760
#define OFF_A32  0
#define OFF_SA   (2 * A32_BUF)            // 16384
#define OFF_SB   (OFF_SA + 3 * SA_SPL)    // 31744
#define SMEM_SZ  (OFF_SB + 3 * SB_STAGE)  // 193024

// ============================ PTX helpers ============================
__device__ __forceinline__ uint32_t smem_u32(const void* p) {
    uint32_t a;
    asm("{ .reg .u64 t; cvta.to.shared.u64 t, %1; cvt.u32.u64 %0, t; }" : "=r"(a) : "l"(p));
    return a;
}
__device__ __forceinline__ void cp16(uint32_t dst, const void* src) {
    asm volatile("cp.async.cg.shared.global [%0], [%1], 16;" :: "r"(dst), "l"(src) : "memory");
}
__device__ __forceinline__ void ldsm_x4(uint32_t* r, uint32_t addr) {
    asm volatile("ldmatrix.sync.aligned.m8n8.x4.shared.b16 {%0,%1,%2,%3}, [%4];"
        : "=r"(r[0]), "=r"(r[1]), "=r"(r[2]), "=r"(r[3]) : "r"(addr));
}
__device__ __forceinline__ void ldsm_x2(uint32_t* r, uint32_t addr) {
    asm volatile("ldmatrix.sync.aligned.m8n8.x2.shared.b16 {%0,%1}, [%2];"
        : "=r"(r[0]), "=r"(r[1]) : "r"(addr));
}
__device__ __forceinline__ void mma16816(float* d, const uint32_t* a, const uint32_t* b) {
    asm volatile("mma.sync.aligned.m16n8k16.row.col.f32.bf16.bf16.f32 "
        "{%0,%1,%2,%3}, {%4,%5,%6,%7}, {%8,%9}, {%0,%1,%2,%3};"
        : "+f"(d[0]), "+f"(d[1]), "+f"(d[2]), "+f"(d[3])
        : "r"(a[0]), "r"(a[1]), "r"(a[2]), "r"(a[3]), "r"(b[0]), "r"(b[1]));
}
// warp tile 32M x 56N: aF[8] (2 m-tiles), bF[14] (6 n8-tiles via x4 + 1 via x2)
__device__ __forceinline__ void mma_tile(float* p, const uint32_t* aF, const uint32_t* bF) {
    #pragma unroll
    for (int mt = 0; mt < 2; mt++)
        #pragma unroll
        for (int nt = 0; nt < 7; nt++) {
            const uint32_t* b = (nt < 6) ? (bF + (nt >> 1) * 4 + (nt & 1) * 2) : (bF + 12);
            mma16816(p + (mt * 7 + nt) * 4, aF + mt * 4, b);
        }
}

// ============================ kernels ============================

// B pre-split: 3-way bf16 (identical math to the passing R8 split)
__global__ void convert_split3_W(const float* __restrict__ src,
                                 __nv_bfloat16* __restrict__ d0,
                                 __nv_bfloat16* __restrict__ d1,
                                 __nv_bfloat16* __restrict__ d2) {
    size_t m = blockIdx.x;
    const float* s = src + m * I_;
    size_t off = m * KPAD;
    for (int k = threadIdx.x; k < I_; k += blockDim.x) {
        float a = s[k];
        __nv_bfloat16 b0 = __float2bfloat16_rn(a);
        float r1 = a - __bfloat162float(b0);
        __nv_bfloat16 b1 = __float2bfloat16_rn(r1);
        float r2 = r1 - __bfloat162float(b1);
        d0[off + k] = b0;
        d1[off + k] = b1;
        d2[off + k] = __float2bfloat16_rn(r2);
    }
}

// Fused fp32-A-load + 3-way-split + bf16x3 mma.sync GEMM.
// CTA 64M x 224N, 8 warps (2M x 4N), warp tile 32x56.
// A pointer passed as a plain kernel parameter (R9 bug: broken __constant__ linkage).
__global__ __launch_bounds__(256, 1) void snn_gemm_mma(const float* __restrict__ gA) {
    extern __shared__ char smem[];
    const uint32_t sb = smem_u32(smem);
    const int tid    = threadIdx.x;
    const int lane   = tid & 31;
    const int wid    = tid >> 5;
    const int warp_m = wid & 1;
    const int warp_n = wid >> 1;
    const int m0     = blockIdx.y * MT;
    const int n0     = blockIdx.x * NT;

    const __nv_bfloat16* gB[3] = {g_W0, g_W1, g_W2};

    // ldmatrix bases
    const uint32_t aoff = (uint32_t)(warp_m * 32 + (lane & 15)) * ROWB + ((lane >> 4) << 4);
    const uint32_t boff_col = (uint32_t)(((lane >> 3) & 1) << 4);
    const uint32_t brow     = (uint32_t)(warp_n * 56 + (lane & 7) + ((lane >> 4) << 3));
    const uint32_t brow_x2  = (uint32_t)(warp_n * 56 + 48 + (lane & 7));
    const uint32_t boff_x2  = brow_x2 * ROWB + (uint32_t)(((lane >> 3) & 1) << 4);

    float acc[56];
    #pragma unroll
    for (int e = 0; e < 56; e++) acc[e] = 0.0f;

    // ---- chunk loader: A fp32 (512 cp16) + B splits (2688 cp16) ----
    auto load_chunk = [&](int c) {
        const uint32_t abuf = sb + OFF_A32 + (uint32_t)(c & 1) * A32_BUF;
        const uint32_t bbuf = sb + OFF_SB + (uint32_t)(c % 3) * SB_STAGE;
        #pragma unroll
        for (int it = 0; it < 13; it++) {
            int idx = tid + it * 256;
            if (idx < 512) {                       // A fp32: 64 rows x 8 slots of 16B
                int r = idx >> 3, sl = idx & 7;
                uint32_t dst = abuf + r * 128 + sl * 16;
                if (c == NCH - 1 && sl == 7) {     // k 700..703 pad
                    *reinterpret_cast<uint4*>(smem + (dst - sb)) = make_uint4(0, 0, 0, 0);
                } else {
                    const void* src = (const char*)gA + ((size_t)(m0 + r) * I_ + c * KCH) * 4 + sl * 16;
                    cp16(dst, src);
                }
            } else if (idx < 3200) {               // B: 3 splits x 224 rows x 4 slots
                int q = idx - 512;
                int j = q / 896, rem = q % 896;
                int r = rem >> 2, sl = rem & 3;
                const void* src = (const char*)gB[j] + ((size_t)(n0 + r) * KPAD + c * KCH) * 2 + sl * 16;
                cp16(bbuf + j * SB_SPL + r * ROWB + sl * 16, src);
            }
        }
        asm volatile("cp.async.commit_group;" ::: "memory");
    };

    load_chunk(0);
    load_chunk(1);

    for (int c = 0; c < NCH; c++) {
        if (c == NCH - 1) asm volatile("cp.async.wait_group 0;" ::: "memory");
        else              asm volatile("cp.async.wait_group 1;" ::: "memory");
        __syncthreads();

        // ---- convert A fp32 chunk -> 3 bf16 split tiles ----
        {
            const char* a32 = smem + OFF_A32 + (c & 1) * A32_BUF;
            int r = tid >> 2, sl = tid & 3;            // row, 8-elem block
            float4 v0 = *reinterpret_cast<const float4*>(a32 + r * 128 + sl * 32);
            float4 v1 = *reinterpret_cast<const float4*>(a32 + r * 128 + sl * 32 + 16);
            float av[8] = {v0.x, v0.y, v0.z, v0.w, v1.x, v1.y, v1.z, v1.w};
            uint16_t s0[8], s1[8], s2[8];
            #pragma unroll
            for (int i = 0; i < 8; i++) {
                float a = av[i];
                __nv_bfloat16 b0 = __float2bfloat16_rn(a);
                float r1 = a - __bfloat162float(b0);
                __nv_bfloat16 b1 = __float2bfloat16_rn(r1);
                float r2 = r1 - __bfloat162float(b1);
                __nv_bfloat16 b2 = __float2bfloat16_rn(r2);
                s0[i] = __bfloat16_as_ushort(b0);
                s1[i] = __bfloat16_as_ushort(b1);
                s2[i] = __bfloat16_as_ushort(b2);
            }
            uint32_t doff = r * ROWB + sl * 16;
            #pragma unroll
            for (int j = 0; j < 3; j++) {
                const uint16_t* s = (j == 0) ? s0 : (j == 1) ? s1 : s2;
                uint4 w;
                w.x = (uint32_t)s[0] | ((uint32_t)s[1] << 16);
                w.y = (uint32_t)s[2] | ((uint32_t)s[3] << 16);
                w.z = (uint32_t)s[4] | ((uint32_t)s[5] << 16);
                w.w = (uint32_t)s[6] | ((uint32_t)s[7] << 16);
                *reinterpret_cast<uint4*>(smem + OFF_SA + j * SA_SPL + doff) = w;
            }
        }
        __syncthreads();

        if (c + 2 < NCH) load_chunk(c + 2);

        // ---- compute: 2 k16 steps, 6 passes each ----
        const uint32_t aB = sb + OFF_SA + aoff;
        const uint32_t bB = sb + OFF_SB + (uint32_t)(c % 3) * SB_STAGE;

        float p[56];
        #pragma unroll
        for (int e = 0; e < 56; e++) p[e] = 0.0f;

        #pragma unroll
        for (int step = 0; step < 2; step++) {
            const uint32_t ks = step * 32;
            uint32_t aF0[8], aFx[8], bF0[14], bFx[14];

            ldsm_x4(aF0 + 0, aB + 0 * SA_SPL + ks);
            ldsm_x4(aF0 + 4, aB + 0 * SA_SPL + 16 * ROWB + ks);
            ldsm_x4(aFx + 0, aB + 1 * SA_SPL + ks);
            ldsm_x4(aFx + 4, aB + 1 * SA_SPL + 16 * ROWB + ks);
            #pragma unroll
            for (int q = 0; q < 3; q++) {
                uint32_t ro = (brow + q * 16) * ROWB + boff_col;
                ldsm_x4(bF0 + 4 * q, bB + 0 * SB_SPL + ro + ks);
                ldsm_x4(bFx + 4 * q, bB + 1 * SB_SPL + ro + ks);
            }
            ldsm_x2(bF0 + 12, bB + 0 * SB_SPL + boff_x2 + ks);
            ldsm_x2(bFx + 12, bB + 1 * SB_SPL + boff_x2 + ks);

            mma_tile(p, aF0, bF0);   // A0*B0
            mma_tile(p, aF0, bFx);   // A0*B1
            mma_tile(p, aFx, bF0);   // A1*B0
            mma_tile(p, aFx, bFx);   // A1*B1

            ldsm_x4(aFx + 0, aB + 2 * SA_SPL + ks);
            ldsm_x4(aFx + 4, aB + 2 * SA_SPL + 16 * ROWB + ks);
            #pragma unroll
            for (int q = 0; q < 3; q++) {
                uint32_t ro = (brow + q * 16) * ROWB + boff_col;
                ldsm_x4(bFx + 4 * q, bB + 2 * SB_SPL + ro + ks);
            }
            ldsm_x2(bFx + 12, bB + 2 * SB_SPL + boff_x2 + ks);

            mma_tile(p, aF0, bFx);   // A0*B2
            mma_tile(p, aFx, bF0);   // A2*B0
        }

        // plain master fold (22 chunks -> sigma ~1.4u, << sigma_ref)
        #pragma unroll
        for (int e = 0; e < 56; e++) acc[e] = __fadd_rn(acc[e], p[e]);
        __syncthreads();
    }

    // ---- store ----
    #pragma unroll
    for (int mt = 0; mt < 2; mt++) {
        #pragma unroll
        for (int nt = 0; nt < 7; nt++) {
            const float* e = acc + (mt * 7 + nt) * 4;
            int m = m0 + warp_m * 32 + mt * 16 + (lane >> 2);
            int n = n0 + warp_n * 56 + nt * 8 + (lane & 3) * 2;
            if (n < O_) {
                *reinterpret_cast<float2*>(g_h + (size_t)m * O_ + n)       = make_float2(e[0], e[1]);
                *reinterpret_cast<float2*>(g_h + (size_t)(m + 8) * O_ + n) = make_float2(e[2], e[3]);
            }
        }
    }
}

// One thread per (b, o) neuron; sequential over t. (Unchanged, proven.)
__global__ __launch_bounds__(256) void snn_scan_kernel(float* __restrict__ out) {
    int idx = blockIdx.x * blockDim.x + threadIdx.x;
    if (idx >= B_ * O_) return;
    int b = idx / O_;
    int o = idx - b * O_;

    const float* hp = g_h + (size_t)b * T_ * O_ + o;
    float* op = out + (size_t)b * T_ * O_ + o;

    float syn = 0.0f, mem = 0.0f;
    #pragma unroll 4
    for (int t = 0; t < T_; t++) {
        float ht = __ldg(hp + (size_t)t * O_);
        float s  = (mem > 1.0f) ? 1.0f : 0.0f;
        op[(size_t)t * O_] = s;
        float nsyn = __fmaf_rn(0.9f, syn, ht);
        float bmv  = __fmaf_rn(0.85f, mem, syn);
        mem = __fmul_rn(bmv, __fadd_rn(1.0f, -s));
        syn = nsyn;
    }
}

// ============================ host ============================
extern "C" void kernel_launch(void* const* d_in, const int* in_sizes, int n_in,
                              void* d_out, int out_size) {
    const float* inputs = (const float*)d_in[0];  // [256,500,700] f32
    const float* W      = (const float*)d_in[1];  // [400,700]     f32
    float* out          = (float*)d_out;          // [256,500,400] f32

    void *pW0, *pW1, *pW2;
    cudaGetSymbolAddress(&pW0, g_W0);
    cudaGetSymbolAddress(&pW1, g_W1);
    cudaGetSymbolAddress(&pW2, g_W2);

    convert_split3_W<<<O_, 256>>>(W, (__nv_bfloat16*)pW0, (__nv_bfloat16*)pW1, (__nv_bfloat16*)pW2);

    cudaFuncSetAttribute(snn_gemm_mma, cudaFuncAttributeMaxDynamicSharedMemorySize, SMEM_SZ);
    dim3 grid(2, M_ / MT);    // 2 N-tiles x 2000 M-tiles
    snn_gemm_mma<<<grid, 256, SMEM_SZ>>>(inputs);

    int n_neurons = B_ * O_;
    snn_scan_kernel<<<(n_neurons + 255) / 256, 256>>>(out);
}

// round 11
// speedup vs baseline: 6.1240x; 1.6125x over previous
#include <cuda_runtime.h>
#include <cuda_fp16.h>
#include <cstdint>

#define B_    256
#define T_    500
#define I_    700
#define O_    400
#define M_    (B_ * T_)        // 128000
#define KPAD  704
#define NPAD  448
#define MT    64               // CTA tile M
#define NT    224              // CTA tile N
#define KCH   32               // k per chunk
#define NCH   22               // 704/32

#define WSCALE    4096.0f          // 2^12, exact
#define WSCALE_INV 0.000244140625f // 2^-12, exact

// ---- device scratch (BSS zero-init; padding regions stay 0) ----
__device__ float  g_h [(size_t)M_ * O_];
__device__ __half g_W0[(size_t)NPAD * KPAD];
__device__ __half g_W1[(size_t)NPAD * KPAD];

// ---- smem geometry ----
#define ROWB     80                       // 64B k-data + 16B pad (ldmatrix conflict-free)
#define A32_BUF  8192                     // 64 rows x 128B fp32
#define SA_SPL   (MT * ROWB)              // 5120 per split
#define SB_SPL   (NT * ROWB)              // 17920 per split
#define SB_STAGE (2 * SB_SPL)             // 35840 (2 splits)
#define OFF_A32  0
#define OFF_SA   (2 * A32_BUF)            // 16384 (2 splits follow)
#define OFF_SB   (OFF_SA + 2 * SA_SPL)    // 26624
#define SMEM_SZ  (OFF_SB + 3 * SB_STAGE)  // 134144

// ============================ PTX helpers ============================
__device__ __forceinline__ uint32_t smem_u32(const void* p) {
    uint32_t a;
    asm("{ .reg .u64 t; cvta.to.shared.u64 t, %1; cvt.u32.u64 %0, t; }" : "=r"(a) : "l"(p));
    return a;
}
__device__ __forceinline__ void cp16(uint32_t dst, const void* src) {
    asm volatile("cp.async.cg.shared.global [%0], [%1], 16;" :: "r"(dst), "l"(src) : "memory");
}
__device__ __forceinline__ void ldsm_x4(uint32_t* r, uint32_t addr) {
    asm volatile("ldmatrix.sync.aligned.m8n8.x4.shared.b16 {%0,%1,%2,%3}, [%4];"
        : "=r"(r[0]), "=r"(r[1]), "=r"(r[2]), "=r"(r[3]) : "r"(addr));
}
__device__ __forceinline__ void ldsm_x2(uint32_t* r, uint32_t addr) {
    asm volatile("ldmatrix.sync.aligned.m8n8.x2.shared.b16 {%0,%1}, [%2];"
        : "=r"(r[0]), "=r"(r[1]) : "r"(addr));
}
__device__ __forceinline__ void mma16816(float* d, const uint32_t* a, const uint32_t* b) {
    asm volatile("mma.sync.aligned.m16n8k16.row.col.f32.f16.f16.f32 "
        "{%0,%1,%2,%3}, {%4,%5,%6,%7}, {%8,%9}, {%0,%1,%2,%3};"
        : "+f"(d[0]), "+f"(d[1]), "+f"(d[2]), "+f"(d[3])
        : "r"(a[0]), "r"(a[1]), "r"(a[2]), "r"(a[3]), "r"(b[0]), "r"(b[1]));
}
// warp tile 32M x 56N: aF[8] (2 m-tiles), bF[14] (6 n8-tiles via x4 + 1 via x2)
__device__ __forceinline__ void mma_tile(float* p, const uint32_t* aF, const uint32_t* bF) {
    #pragma unroll
    for (int mt = 0; mt < 2; mt++)
        #pragma unroll
        for (int nt = 0; nt < 7; nt++) {
            const uint32_t* b = (nt < 6) ? (bF + (nt >> 1) * 4 + (nt & 1) * 2) : (bF + 12);
            mma16816(p + (mt * 7 + nt) * 4, aF + mt * 4, b);
        }
}

// ============================ kernels ============================

// W pre-split: scale by 2^12 (exact), then 2-way fp16 split.
__global__ void convert_split2_W(const float* __restrict__ src,
                                 __half* __restrict__ d0,
                                 __half* __restrict__ d1) {
    size_t m = blockIdx.x;
    const float* s = src + m * I_;
    size_t off = m * KPAD;
    for (int k = threadIdx.x; k < I_; k += blockDim.x) {
        float a = s[k] * WSCALE;            // exact power-of-2 scale
        __half h0 = __float2half_rn(a);
        float r1 = a - __half2float(h0);
        d0[off + k] = h0;
        d1[off + k] = __float2half_rn(r1);
    }
}

// Fused fp32-A-load + 2-way-fp16-split + 3-pass mma.sync GEMM.
// CTA 64M x 224N, 8 warps (2M x 4N), warp tile 32x56.
__global__ __launch_bounds__(256, 1) void snn_gemm_mma(const float* __restrict__ gA) {
    extern __shared__ char smem[];
    const uint32_t sb = smem_u32(smem);
    const int tid    = threadIdx.x;
    const int lane   = tid & 31;
    const int wid    = tid >> 5;
    const int warp_m = wid & 1;
    const int warp_n = wid >> 1;
    const int m0     = blockIdx.y * MT;
    const int n0     = blockIdx.x * NT;

    const __half* gB[2] = {g_W0, g_W1};

    // ldmatrix bases
    const uint32_t aoff = (uint32_t)(warp_m * 32 + (lane & 15)) * ROWB + ((lane >> 4) << 4);
    const uint32_t boff_col = (uint32_t)(((lane >> 3) & 1) << 4);
    const uint32_t brow     = (uint32_t)(warp_n * 56 + (lane & 7) + ((lane >> 4) << 3));
    const uint32_t brow_x2  = (uint32_t)(warp_n * 56 + 48 + (lane & 7));
    const uint32_t boff_x2  = brow_x2 * ROWB + (uint32_t)(((lane >> 3) & 1) << 4);

    float acc[56];
    #pragma unroll
    for (int e = 0; e < 56; e++) acc[e] = 0.0f;

    // ---- chunk loader: A fp32 (512 cp16) + B splits (1792 cp16) = 2304 ----
    auto load_chunk = [&](int c) {
        const uint32_t abuf = sb + OFF_A32 + (uint32_t)(c & 1) * A32_BUF;
        const uint32_t bbuf = sb + OFF_SB + (uint32_t)(c % 3) * SB_STAGE;
        #pragma unroll
        for (int it = 0; it < 9; it++) {
            int idx = tid + it * 256;
            if (idx < 512) {                       // A fp32: 64 rows x 8 slots of 16B
                int r = idx >> 3, sl = idx & 7;
                uint32_t dst = abuf + r * 128 + sl * 16;
                if (c == NCH - 1 && sl == 7) {     // k 700..703 pad
                    *reinterpret_cast<uint4*>(smem + (dst - sb)) = make_uint4(0, 0, 0, 0);
                } else {
                    const void* src = (const char*)gA + ((size_t)(m0 + r) * I_ + c * KCH) * 4 + sl * 16;
                    cp16(dst, src);
                }
            } else {                               // B: 2 splits x 224 rows x 4 slots
                int q = idx - 512;
                int j = q / 896, rem = q % 896;
                int r = rem >> 2, sl = rem & 3;
                const void* src = (const char*)gB[j] + ((size_t)(n0 + r) * KPAD + c * KCH) * 2 + sl * 16;
                cp16(bbuf + j * SB_SPL + r * ROWB + sl * 16, src);
            }
        }
        asm volatile("cp.async.commit_group;" ::: "memory");
    };

    load_chunk(0);
    load_chunk(1);

    for (int c = 0; c < NCH; c++) {
        if (c == NCH - 1) asm volatile("cp.async.wait_group 0;" ::: "memory");
        else              asm volatile("cp.async.wait_group 1;" ::: "memory");
        __syncthreads();

        // ---- convert A fp32 chunk -> 2 fp16 split tiles ----
        {
            const char* a32 = smem + OFF_A32 + (c & 1) * A32_BUF;
            int r = tid >> 2, sl = tid & 3;            // row, 8-elem block
            float4 v0 = *reinterpret_cast<const float4*>(a32 + r * 128 + sl * 32);
            float4 v1 = *reinterpret_cast<const float4*>(a32 + r * 128 + sl * 32 + 16);
            float av[8] = {v0.x, v0.y, v0.z, v0.w, v1.x, v1.y, v1.z, v1.w};
            uint16_t s0[8], s1[8];
            #pragma unroll
            for (int i = 0; i < 8; i++) {
                float a = av[i];
                __half h0 = __float2half_rn(a);
                float r1 = a - __half2float(h0);
                __half h1 = __float2half_rn(r1);
                s0[i] = __half_as_ushort(h0);
                s1[i] = __half_as_ushort(h1);
            }
            uint32_t doff = r * ROWB + sl * 16;
            #pragma unroll
            for (int j = 0; j < 2; j++) {
                const uint16_t* s = (j == 0) ? s0 : s1;
                uint4 w;
                w.x = (uint32_t)s[0] | ((uint32_t)s[1] << 16);
                w.y = (uint32_t)s[2] | ((uint32_t)s[3] << 16);
                w.z = (uint32_t)s[4] | ((uint32_t)s[5] << 16);
                w.w = (uint32_t)s[6] | ((uint32_t)s[7] << 16);
                *reinterpret_cast<uint4*>(smem + OFF_SA + j * SA_SPL + doff) = w;
            }
        }
        __syncthreads();

        if (c + 2 < NCH) load_chunk(c + 2);

        // ---- compute: 2 k16 steps, 3 passes each (00, 01, 10) ----
        const uint32_t aB = sb + OFF_SA + aoff;
        const uint32_t bB = sb + OFF_SB + (uint32_t)(c % 3) * SB_STAGE;

        float p[56];
        #pragma unroll
        for (int e = 0; e < 56; e++) p[e] = 0.0f;

        #pragma unroll
        for (int step = 0; step < 2; step++) {
            const uint32_t ks = step * 32;
            uint32_t aF0[8], aF1[8], bF0[14], bF1[14];

            ldsm_x4(aF0 + 0, aB + 0 * SA_SPL + ks);
            ldsm_x4(aF0 + 4, aB + 0 * SA_SPL + 16 * ROWB + ks);
            ldsm_x4(aF1 + 0, aB + 1 * SA_SPL + ks);
            ldsm_x4(aF1 + 4, aB + 1 * SA_SPL + 16 * ROWB + ks);
            #pragma unroll
            for (int q = 0; q < 3; q++) {
                uint32_t ro = (brow + q * 16) * ROWB + boff_col;
                ldsm_x4(bF0 + 4 * q, bB + 0 * SB_SPL + ro + ks);
                ldsm_x4(bF1 + 4 * q, bB + 1 * SB_SPL + ro + ks);
            }
            ldsm_x2(bF0 + 12, bB + 0 * SB_SPL + boff_x2 + ks);
            ldsm_x2(bF1 + 12, bB + 1 * SB_SPL + boff_x2 + ks);

            mma_tile(p, aF0, bF0);   // A0*B0
            mma_tile(p, aF0, bF1);   // A0*B1
            mma_tile(p, aF1, bF0);   // A1*B0
        }

        // plain master fold (22 chunks -> sigma ~1.4u)
        #pragma unroll
        for (int e = 0; e < 56; e++) acc[e] = __fadd_rn(acc[e], p[e]);
        __syncthreads();
    }

    // ---- store (undo W scale by exact 2^-12) ----
    #pragma unroll
    for (int mt = 0; mt < 2; mt++) {
        #pragma unroll
        for (int nt = 0; nt < 7; nt++) {
            const float* e = acc + (mt * 7 + nt) * 4;
            int m = m0 + warp_m * 32 + mt * 16 + (lane >> 2);
            int n = n0 + warp_n * 56 + nt * 8 + (lane & 3) * 2;
            if (n < O_) {
                *reinterpret_cast<float2*>(g_h + (size_t)m * O_ + n) =
                    make_float2(e[0] * WSCALE_INV, e[1] * WSCALE_INV);
                *reinterpret_cast<float2*>(g_h + (size_t)(m + 8) * O_ + n) =
                    make_float2(e[2] * WSCALE_INV, e[3] * WSCALE_INV);
            }
        }
    }
}

// One thread per (b, o) neuron; sequential over t. (Unchanged, proven.)
__global__ __launch_bounds__(256) void snn_scan_kernel(float* __restrict__ out) {
    int idx = blockIdx.x * blockDim.x + threadIdx.x;
    if (idx >= B_ * O_) return;
    int b = idx / O_;
    int o = idx - b * O_;

    const float* hp = g_h + (size_t)b * T_ * O_ + o;
    float* op = out + (size_t)b * T_ * O_ + o;

    float syn = 0.0f, mem = 0.0f;
    #pragma unroll 4
    for (int t = 0; t < T_; t++) {
        float ht = __ldg(hp + (size_t)t * O_);
        float s  = (mem > 1.0f) ? 1.0f : 0.0f;
        op[(size_t)t * O_] = s;
        float nsyn = __fmaf_rn(0.9f, syn, ht);
        float bmv  = __fmaf_rn(0.85f, mem, syn);
        mem = __fmul_rn(bmv, __fadd_rn(1.0f, -s));
        syn = nsyn;
    }
}

// ============================ host ============================
extern "C" void kernel_launch(void* const* d_in, const int* in_sizes, int n_in,
                              void* d_out, int out_size) {
    const float* inputs = (const float*)d_in[0];  // [256,500,700] f32
    const float* W      = (const float*)d_in[1];  // [400,700]     f32
    float* out          = (float*)d_out;          // [256,500,400] f32

    void *pW0, *pW1;
    cudaGetSymbolAddress(&pW0, g_W0);
    cudaGetSymbolAddress(&pW1, g_W1);

    convert_split2_W<<<O_, 256>>>(W, (__half*)pW0, (__half*)pW1);

    cudaFuncSetAttribute(snn_gemm_mma, cudaFuncAttributeMaxDynamicSharedMemorySize, SMEM_SZ);
    dim3 grid(2, M_ / MT);    // 2 N-tiles x 2000 M-tiles
    snn_gemm_mma<<<grid, 256, SMEM_SZ>>>(inputs);

    int n_neurons = B_ * O_;
    snn_scan_kernel<<<(n_neurons + 255) / 256, 256>>>(out);
}